// round 16
// baseline (speedup 1.0000x reference)
#include <cuda_runtime.h>
#include <cuda_fp16.h>

#define MAX_NODES 500000
#define MAX_GRAPHS 8192
#define FDIM 16

__device__ int    g_cnt_i[MAX_NODES];            // in-degree (memset 0)
__device__ __half g_h[MAX_NODES * FDIM];         // features * dinv (fp16)
__device__ __half g_agg_h[MAX_NODES * FDIM];     // fp16 accumulator (init=self term)
__device__ float  g_pool[MAX_GRAPHS * FDIM];
__device__ float  g_gcnt[MAX_GRAPHS];

__device__ __forceinline__ void red_v4f(float* addr, float4 v) {
    asm volatile("red.global.add.v4.f32 [%0], {%1,%2,%3,%4};"
                 :: "l"(addr), "f"(v.x), "f"(v.y), "f"(v.z), "f"(v.w)
                 : "memory");
}

__device__ __forceinline__ void red_v4h2(__half* addr, uint4 u) {
    asm volatile("red.global.add.noftz.v4.f16x2 [%0], {%1,%2,%3,%4};"
                 :: "l"(addr), "r"(u.x), "r"(u.y), "r"(u.z), "r"(u.w)
                 : "memory");
}

// pack 16 scaled fp32 -> 32B fp16
__device__ __forceinline__ void store_h16(__half* dst, const float* s, float di) {
    __align__(16) __half2 hh[8];
#pragma unroll
    for (int q = 0; q < 8; q++)
        hh[q] = __floats2half2_rn(s[2 * q] * di, s[2 * q + 1] * di);
    *(uint4*)dst       = *(uint4*)&hh[0];
    *(uint4*)(dst + 8) = *(uint4*)&hh[4];
}

// load 16 fp16 -> fp32
__device__ __forceinline__ void load_h16(const __half* src, float* f) {
    uint4 u0 = *(const uint4*)src;
    uint4 u1 = *(const uint4*)(src + 8);
    const unsigned* uu[8] = {&u0.x,&u0.y,&u0.z,&u0.w,&u1.x,&u1.y,&u1.z,&u1.w};
#pragma unroll
    for (int q = 0; q < 8; q++) {
        float2 p = __half22float2(*(const __half2*)uu[q]);
        f[2*q] = p.x; f[2*q+1] = p.y;
    }
}

// 1) in-degree count over targets (scalar, 256 thr) + zero pool buffers
__global__ void k_count(const int* __restrict__ cols, int E, int G) {
    int e = blockIdx.x * blockDim.x + threadIdx.x;
    if (e < G * FDIM) g_pool[e] = 0.0f;      // consumed only after scatter2
    if (e < G) g_gcnt[e] = 0.0f;
    if (e < E) atomicAdd(&g_cnt_i[cols[e]], 1);
}

// 2) layer1: s = x@W1 ; g_h = g_agg_h = fp16(s*di)
__global__ void k_layer1(const float* __restrict__ x, const float* __restrict__ W1,
                         int N) {
    __shared__ float sx[128 * 9];
    int base = blockIdx.x * 128;
    int n = base + threadIdx.x;
    int lim = min(128, N - base) * 9;
    for (int i = threadIdx.x; i < lim; i += 128)
        sx[i] = x[(long long)base * 9 + i];
    __syncthreads();
    if (n >= N) return;
    float xi[9];
#pragma unroll
    for (int k = 0; k < 9; k++) xi[k] = sx[threadIdx.x * 9 + k];
    float di = rsqrtf((float)g_cnt_i[n] + 1.0f);
    float s[FDIM];
#pragma unroll
    for (int f = 0; f < FDIM; f++) {
        float acc = 0.0f;
#pragma unroll
        for (int k = 0; k < 9; k++) acc += xi[k] * __ldg(&W1[k * FDIM + f]);
        s[f] = acc;
    }
    store_h16(&g_h[n * FDIM], s, di);
    store_h16(&g_agg_h[n * FDIM], s, di);
}

// 3/5) scatter: agg[c] += g_h[r]; ONE thread/edge:
//      r,c loaded once; two independent 16B loads + two independent v4.f16x2 reds.
__global__ void k_scatter(const int* __restrict__ rows,
                          const int* __restrict__ cols, int E) {
    int e = blockIdx.x * blockDim.x + threadIdx.x;
    if (e >= E) return;
    int r = __ldg(&rows[e]);
    int c = __ldg(&cols[e]);
    const __half* src = &g_h[r * FDIM];
    __half* dst = &g_agg_h[c * FDIM];
    uint4 u0 = *(const uint4*)src;
    uint4 u1 = *(const uint4*)(src + 8);
    red_v4h2(dst, u0);
    red_v4h2(dst + 8, u1);
}

// 4) transform: a = relu(agg*di + b1); s = a@W2; g_h = g_agg_h = fp16(s*di)
__global__ void k_transform(const float* __restrict__ b1, const float* __restrict__ W2,
                            int N) {
    __shared__ float sW[FDIM * FDIM];
    __shared__ float sb[FDIM];
    if (threadIdx.x < FDIM * FDIM) sW[threadIdx.x] = W2[threadIdx.x];
    if (threadIdx.x < FDIM) sb[threadIdx.x] = b1[threadIdx.x];
    __syncthreads();
    int n = blockIdx.x * blockDim.x + threadIdx.x;
    if (n >= N) return;
    float di = rsqrtf((float)g_cnt_i[n] + 1.0f);
    float f[FDIM], a[FDIM];
    load_h16(&g_agg_h[n * FDIM], f);
#pragma unroll
    for (int k = 0; k < FDIM; k++)
        a[k] = fmaxf(f[k] * di + sb[k], 0.0f);
    float s[FDIM];
#pragma unroll
    for (int ff = 0; ff < FDIM; ff++) {
        float acc = 0.0f;
#pragma unroll
        for (int k = 0; k < FDIM; k++) acc += a[k] * sW[k * FDIM + ff];
        s[ff] = acc;
    }
    store_h16(&g_h[n * FDIM], s, di);
    store_h16(&g_agg_h[n * FDIM], s, di);
}

// 6) pool: relu(agg*di + b2) -> fp32 red.v4 per graph; 4 lanes/node
__global__ void k_pool(const int* __restrict__ batch,
                       const float* __restrict__ b2, int N) {
    long long idx = (long long)blockIdx.x * blockDim.x + threadIdx.x;
    int n = (int)(idx >> 2);
    int q = (int)(idx & 3);
    if (n >= N) return;
    float di = rsqrtf((float)g_cnt_i[n] + 1.0f);
    int g = __ldg(&batch[n]);
    uint2 u = *(const uint2*)&g_agg_h[n * FDIM + q * 4];
    float2 f0 = __half22float2(*(__half2*)&u.x);
    float2 f1 = __half22float2(*(__half2*)&u.y);
    float4 a = make_float4(fmaxf(f0.x * di + __ldg(&b2[q*4+0]), 0.0f),
                           fmaxf(f0.y * di + __ldg(&b2[q*4+1]), 0.0f),
                           fmaxf(f1.x * di + __ldg(&b2[q*4+2]), 0.0f),
                           fmaxf(f1.y * di + __ldg(&b2[q*4+3]), 0.0f));
    red_v4f(&g_pool[g * FDIM + q * 4], a);
    if (q == 0) atomicAdd(&g_gcnt[g], 1.0f);
}

// 7) MLP head
__global__ void k_mlp(const float* __restrict__ meta,
                      const float* __restrict__ Wh1, const float* __restrict__ bh1,
                      const float* __restrict__ Wh2, const float* __restrict__ bh2,
                      float* __restrict__ out, int G) {
    int g = blockIdx.x * blockDim.x + threadIdx.x;
    if (g >= G) return;
    float inv = 1.0f / fmaxf(g_gcnt[g], 1.0f);
    float z[FDIM];
#pragma unroll
    for (int f = 0; f < FDIM; f++) z[f] = __ldg(&bh1[f]);
#pragma unroll
    for (int k = 0; k < FDIM; k++) {
        float e = g_pool[g * FDIM + k] * inv;
#pragma unroll
        for (int f = 0; f < FDIM; f++) z[f] += e * __ldg(&Wh1[k * FDIM + f]);
    }
    for (int k = 0; k < 27; k++) {
        float m = meta[g * 27 + k];
#pragma unroll
        for (int f = 0; f < FDIM; f++) z[f] += m * __ldg(&Wh1[(FDIM + k) * FDIM + f]);
    }
    float o = __ldg(&bh2[0]);
#pragma unroll
    for (int f = 0; f < FDIM; f++) o += fmaxf(z[f], 0.0f) * __ldg(&Wh2[f]);
    out[g] = o;
}

extern "C" void kernel_launch(void* const* d_in, const int* in_sizes, int n_in,
                              void* d_out, int out_size) {
    const float* x    = (const float*)d_in[0];
    const int*   ei   = (const int*)d_in[1];
    const int*   batch= (const int*)d_in[2];
    const float* meta = (const float*)d_in[3];
    const float* W1   = (const float*)d_in[4];
    const float* b1   = (const float*)d_in[5];
    const float* W2   = (const float*)d_in[6];
    const float* b2   = (const float*)d_in[7];
    const float* Wh1  = (const float*)d_in[8];
    const float* bh1  = (const float*)d_in[9];
    const float* Wh2  = (const float*)d_in[10];
    const float* bh2  = (const float*)d_in[11];
    float* out = (float*)d_out;

    const int N = in_sizes[0] / 9;
    const int E = in_sizes[1] / 2;
    const int G = in_sizes[3] / 27;
    const int* rows = ei;      // source
    const int* cols = ei + E;  // target

    const int B = 256;

    void* p_cnt;
    cudaGetSymbolAddress(&p_cnt, g_cnt_i);
    cudaMemsetAsync(p_cnt, 0, (size_t)N * sizeof(int));

    {
        int total = E > G * FDIM ? E : G * FDIM;   // cover pool zeroing too
        k_count<<<(total + B - 1) / B, B>>>(cols, E, G);
    }
    k_layer1<<<(N + 127) / 128, 128>>>(x, W1, N);
    {
        int nb = (E + B - 1) / B;
        k_scatter<<<nb, B>>>(rows, cols, E);
        k_transform<<<(N + B - 1) / B, B>>>(b1, W2, N);
        k_scatter<<<nb, B>>>(rows, cols, E);
    }
    {
        long long t = (long long)N * 4;
        k_pool<<<(int)((t + B - 1) / B), B>>>(batch, b2, N);
    }
    k_mlp<<<(G + B - 1) / B, B>>>(meta, Wh1, bh1, Wh2, bh2, out, G);
}

// round 17
// speedup vs baseline: 1.0987x; 1.0987x over previous
#include <cuda_runtime.h>
#include <cuda_fp16.h>

#define MAX_NODES 500000
#define MAX_GRAPHS 8192
#define FDIM 16

__device__ int    g_cnt_i[MAX_NODES];            // in-degree (memset 0)
__device__ __half g_h[MAX_NODES * FDIM];         // features * dinv (fp16)
__device__ __half g_agg_h[MAX_NODES * FDIM];     // fp16 accumulator (init=self term)
__device__ float  g_pool[MAX_GRAPHS * FDIM];
__device__ float  g_gcnt[MAX_GRAPHS];

__device__ __forceinline__ void red_v4f(float* addr, float4 v) {
    asm volatile("red.global.add.v4.f32 [%0], {%1,%2,%3,%4};"
                 :: "l"(addr), "f"(v.x), "f"(v.y), "f"(v.z), "f"(v.w)
                 : "memory");
}

__device__ __forceinline__ void red_v4h2(__half* addr, uint4 u) {
    asm volatile("red.global.add.noftz.v4.f16x2 [%0], {%1,%2,%3,%4};"
                 :: "l"(addr), "r"(u.x), "r"(u.y), "r"(u.z), "r"(u.w)
                 : "memory");
}

// pack 16 scaled fp32 -> 32B fp16
__device__ __forceinline__ void store_h16(__half* dst, const float* s, float di) {
    __align__(16) __half2 hh[8];
#pragma unroll
    for (int q = 0; q < 8; q++)
        hh[q] = __floats2half2_rn(s[2 * q] * di, s[2 * q + 1] * di);
    *(uint4*)dst       = *(uint4*)&hh[0];
    *(uint4*)(dst + 8) = *(uint4*)&hh[4];
}

// load 16 fp16 -> fp32
__device__ __forceinline__ void load_h16(const __half* src, float* f) {
    uint4 u0 = *(const uint4*)src;
    uint4 u1 = *(const uint4*)(src + 8);
    const unsigned* uu[8] = {&u0.x,&u0.y,&u0.z,&u0.w,&u1.x,&u1.y,&u1.z,&u1.w};
#pragma unroll
    for (int q = 0; q < 8; q++) {
        float2 p = __half22float2(*(const __half2*)uu[q]);
        f[2*q] = p.x; f[2*q+1] = p.y;
    }
}

// 1) in-degree count over targets (scalar, 256 thr) + zero pool buffers
__global__ void k_count(const int* __restrict__ cols, int E, int G) {
    int e = blockIdx.x * blockDim.x + threadIdx.x;
    if (e < G * FDIM) g_pool[e] = 0.0f;      // consumed only after scatter2
    if (e < G) g_gcnt[e] = 0.0f;
    if (e < E) atomicAdd(&g_cnt_i[cols[e]], 1);
}

// 2) layer1: s = x@W1 ; g_h = g_agg_h = fp16(s*di)
__global__ void k_layer1(const float* __restrict__ x, const float* __restrict__ W1,
                         int N) {
    __shared__ float sx[128 * 9];
    int base = blockIdx.x * 128;
    int n = base + threadIdx.x;
    int lim = min(128, N - base) * 9;
    for (int i = threadIdx.x; i < lim; i += 128)
        sx[i] = x[(long long)base * 9 + i];
    __syncthreads();
    if (n >= N) return;
    float xi[9];
#pragma unroll
    for (int k = 0; k < 9; k++) xi[k] = sx[threadIdx.x * 9 + k];
    float di = rsqrtf((float)g_cnt_i[n] + 1.0f);
    float s[FDIM];
#pragma unroll
    for (int f = 0; f < FDIM; f++) {
        float acc = 0.0f;
#pragma unroll
        for (int k = 0; k < 9; k++) acc += xi[k] * __ldg(&W1[k * FDIM + f]);
        s[f] = acc;
    }
    store_h16(&g_h[n * FDIM], s, di);
    store_h16(&g_agg_h[n * FDIM], s, di);
}

// 3/5) scatter: agg[c] += g_h[r]; 2 lanes/edge, 16B fp16 load + one v4.f16x2 red
__global__ void k_scatter(const int* __restrict__ rows,
                          const int* __restrict__ cols, int E) {
    long long idx = (long long)blockIdx.x * blockDim.x + threadIdx.x;
    int e = (int)(idx >> 1);
    int q = (int)(idx & 1);
    if (e >= E) return;
    int r = __ldg(&rows[e]);
    int c = __ldg(&cols[e]);
    uint4 u = *(const uint4*)&g_h[r * FDIM + q * 8];
    red_v4h2(&g_agg_h[c * FDIM + q * 8], u);
}

// 4) transform: a = relu(agg*di + b1); s = a@W2; g_h = g_agg_h = fp16(s*di)
__global__ void k_transform(const float* __restrict__ b1, const float* __restrict__ W2,
                            int N) {
    __shared__ float sW[FDIM * FDIM];
    __shared__ float sb[FDIM];
    if (threadIdx.x < FDIM * FDIM) sW[threadIdx.x] = W2[threadIdx.x];
    if (threadIdx.x < FDIM) sb[threadIdx.x] = b1[threadIdx.x];
    __syncthreads();
    int n = blockIdx.x * blockDim.x + threadIdx.x;
    if (n >= N) return;
    float di = rsqrtf((float)g_cnt_i[n] + 1.0f);
    float f[FDIM], a[FDIM];
    load_h16(&g_agg_h[n * FDIM], f);
#pragma unroll
    for (int k = 0; k < FDIM; k++)
        a[k] = fmaxf(f[k] * di + sb[k], 0.0f);
    float s[FDIM];
#pragma unroll
    for (int ff = 0; ff < FDIM; ff++) {
        float acc = 0.0f;
#pragma unroll
        for (int k = 0; k < FDIM; k++) acc += a[k] * sW[k * FDIM + ff];
        s[ff] = acc;
    }
    store_h16(&g_h[n * FDIM], s, di);
    store_h16(&g_agg_h[n * FDIM], s, di);
}

// 6) pool: relu(agg*di + b2) -> fp32 red.v4 per graph; 4 lanes/node
__global__ void k_pool(const int* __restrict__ batch,
                       const float* __restrict__ b2, int N) {
    long long idx = (long long)blockIdx.x * blockDim.x + threadIdx.x;
    int n = (int)(idx >> 2);
    int q = (int)(idx & 3);
    if (n >= N) return;
    float di = rsqrtf((float)g_cnt_i[n] + 1.0f);
    int g = __ldg(&batch[n]);
    uint2 u = *(const uint2*)&g_agg_h[n * FDIM + q * 4];
    float2 f0 = __half22float2(*(__half2*)&u.x);
    float2 f1 = __half22float2(*(__half2*)&u.y);
    float4 a = make_float4(fmaxf(f0.x * di + __ldg(&b2[q*4+0]), 0.0f),
                           fmaxf(f0.y * di + __ldg(&b2[q*4+1]), 0.0f),
                           fmaxf(f1.x * di + __ldg(&b2[q*4+2]), 0.0f),
                           fmaxf(f1.y * di + __ldg(&b2[q*4+3]), 0.0f));
    red_v4f(&g_pool[g * FDIM + q * 4], a);
    if (q == 0) atomicAdd(&g_gcnt[g], 1.0f);
}

// 7) MLP head
__global__ void k_mlp(const float* __restrict__ meta,
                      const float* __restrict__ Wh1, const float* __restrict__ bh1,
                      const float* __restrict__ Wh2, const float* __restrict__ bh2,
                      float* __restrict__ out, int G) {
    int g = blockIdx.x * blockDim.x + threadIdx.x;
    if (g >= G) return;
    float inv = 1.0f / fmaxf(g_gcnt[g], 1.0f);
    float z[FDIM];
#pragma unroll
    for (int f = 0; f < FDIM; f++) z[f] = __ldg(&bh1[f]);
#pragma unroll
    for (int k = 0; k < FDIM; k++) {
        float e = g_pool[g * FDIM + k] * inv;
#pragma unroll
        for (int f = 0; f < FDIM; f++) z[f] += e * __ldg(&Wh1[k * FDIM + f]);
    }
    for (int k = 0; k < 27; k++) {
        float m = meta[g * 27 + k];
#pragma unroll
        for (int f = 0; f < FDIM; f++) z[f] += m * __ldg(&Wh1[(FDIM + k) * FDIM + f]);
    }
    float o = __ldg(&bh2[0]);
#pragma unroll
    for (int f = 0; f < FDIM; f++) o += fmaxf(z[f], 0.0f) * __ldg(&Wh2[f]);
    out[g] = o;
}

extern "C" void kernel_launch(void* const* d_in, const int* in_sizes, int n_in,
                              void* d_out, int out_size) {
    const float* x    = (const float*)d_in[0];
    const int*   ei   = (const int*)d_in[1];
    const int*   batch= (const int*)d_in[2];
    const float* meta = (const float*)d_in[3];
    const float* W1   = (const float*)d_in[4];
    const float* b1   = (const float*)d_in[5];
    const float* W2   = (const float*)d_in[6];
    const float* b2   = (const float*)d_in[7];
    const float* Wh1  = (const float*)d_in[8];
    const float* bh1  = (const float*)d_in[9];
    const float* Wh2  = (const float*)d_in[10];
    const float* bh2  = (const float*)d_in[11];
    float* out = (float*)d_out;

    const int N = in_sizes[0] / 9;
    const int E = in_sizes[1] / 2;
    const int G = in_sizes[3] / 27;
    const int* rows = ei;      // source
    const int* cols = ei + E;  // target

    const int B = 256;

    void* p_cnt;
    cudaGetSymbolAddress(&p_cnt, g_cnt_i);
    cudaMemsetAsync(p_cnt, 0, (size_t)N * sizeof(int));

    {
        int total = E > G * FDIM ? E : G * FDIM;   // cover pool zeroing too
        k_count<<<(total + B - 1) / B, B>>>(cols, E, G);
    }
    k_layer1<<<(N + 127) / 128, 128>>>(x, W1, N);
    {
        long long t = (long long)E * 2;
        int nb = (int)((t + B - 1) / B);
        k_scatter<<<nb, B>>>(rows, cols, E);
        k_transform<<<(N + B - 1) / B, B>>>(b1, W2, N);
        k_scatter<<<nb, B>>>(rows, cols, E);
    }
    {
        long long t = (long long)N * 4;
        k_pool<<<(int)((t + B - 1) / B), B>>>(batch, b2, N);
    }
    k_mlp<<<(G + B - 1) / B, B>>>(meta, Wh1, bh1, Wh2, bh2, out, G);
}